// round 5
// baseline (speedup 1.0000x reference)
#include <cuda_runtime.h>
#include <cstdint>

// Elman RNN, K-split 2-warp layout.
// N=2048, T=512, I=32, H=64, O=1.
// 1024 blocks x 64 threads (2 warps), 2 samples per block.
// Lane l owns hidden units (2l, 2l+1); warp w contracts k in [48w, 48w+48).
//   k=0..63 -> h (W_hh cols), k=64..95 -> x (W_ih cols).
// Weights: 24 f32x2 pairs per unit x 2 units = 48 ull (96 regs) per thread.
// Per step: FMA half-contractions -> STS partials -> bar -> warp w combines,
// tanh, publishes h/x for sample w -> bar. ~140 regs -> 7 blocks/SM, 1 wave.

#define TT 512

typedef unsigned long long ull;

__device__ __forceinline__ float tanh_acc(float s) {
    float e = __expf(2.0f * s);
    return 1.0f - __fdividef(2.0f, e + 1.0f);
}

__global__ void __launch_bounds__(64, 7) rnn_ksplit_kernel(
    const float* __restrict__ x,      // [N, T, I]
    const float* __restrict__ W_ih,   // [H, I]
    const float* __restrict__ W_hh,   // [H, H]
    const float* __restrict__ b_ih,   // [H]
    const float* __restrict__ b_hh,   // [H]
    const float* __restrict__ fc_w,   // [1, H]
    const float* __restrict__ fc_b,   // [1]
    float* __restrict__ out)          // [N, 1]
{
    __shared__ __align__(16) float buf[2][2][96];   // [parity][sample][ h(64)|x(32) ]
    __shared__ __align__(16) float part[2][2][64];  // [warp][sample][unit]

    const int tid = threadIdx.x;
    const int w   = tid >> 5;         // warp: k-half owner, later sample owner
    const int l   = tid & 31;
    const int u0  = 2 * l;
    const int u1  = u0 + 1;
    const int n0  = 2 * blockIdx.x;

    // ---- per-thread weights: 24 f32x2 pairs per unit over this warp's k-half ----
    ull W0[24], W1[24];
    if (w == 0) {
        // k = 0..47 -> W_hh[u][0..47]
        const ull* p0 = reinterpret_cast<const ull*>(W_hh + u0 * 64);
        const ull* p1 = reinterpret_cast<const ull*>(W_hh + u1 * 64);
        #pragma unroll
        for (int k = 0; k < 24; k++) { W0[k] = __ldg(p0 + k); W1[k] = __ldg(p1 + k); }
    } else {
        // k = 48..63 -> W_hh[u][48..63], k = 64..95 -> W_ih[u][0..31]
        const ull* p0 = reinterpret_cast<const ull*>(W_hh + u0 * 64 + 48);
        const ull* p1 = reinterpret_cast<const ull*>(W_hh + u1 * 64 + 48);
        #pragma unroll
        for (int k = 0; k < 8; k++) { W0[k] = __ldg(p0 + k); W1[k] = __ldg(p1 + k); }
        const ull* q0 = reinterpret_cast<const ull*>(W_ih + u0 * 32);
        const ull* q1 = reinterpret_cast<const ull*>(W_ih + u1 * 32);
        #pragma unroll
        for (int k = 0; k < 16; k++) { W0[8 + k] = __ldg(q0 + k); W1[8 + k] = __ldg(q1 + k); }
    }
    // bias seeded only in warp 0's partial (added exactly once per unit/sample)
    const float bias0 = (w == 0) ? (b_ih[u0] + b_hh[u0]) : 0.0f;
    const float bias1 = (w == 0) ? (b_ih[u1] + b_hh[u1]) : 0.0f;

    // warp w stages x for sample w (coalesced 128B per warp)
    const float* xl = x + (size_t)(n0 + w) * TT * 32 + l;

    // ---- init: h0 = ones, stage x_0 ----
    buf[0][0][tid] = 1.0f;
    buf[0][1][tid] = 1.0f;
    buf[0][w][64 + l] = __ldg(xl);
    __syncthreads();

    float h0 = 1.0f, h1 = 1.0f;       // sample-w h for units u0,u1 (tanh-phase result)
    const int kbase = 48 * w;

    #pragma unroll 2
    for (int t = 0; t < TT; t++) {
        const int cur = t & 1;
        const int nxt = cur ^ 1;

        // prefetch next x at step top: LDG latency hides under the FMA loop
        const int tn = (t + 1 < TT) ? (t + 1) : (TT - 1);
        const float xn = __ldg(xl + tn * 32);

        const ulonglong2* vp0 = reinterpret_cast<const ulonglong2*>(&buf[cur][0][kbase]);
        const ulonglong2* vp1 = reinterpret_cast<const ulonglong2*>(&buf[cur][1][kbase]);

        // 4 f32x2 chains: (unit u0/u1) x (sample 0/1); same-chain spacing 8 cyc
        float2 sa = make_float2(bias0, 0.0f);
        float2 sb = make_float2(bias1, 0.0f);
        ull a00 = *reinterpret_cast<ull*>(&sa);   // u0, sample0
        ull a01 = *reinterpret_cast<ull*>(&sb);   // u1, sample0
        ull a10 = a00;                            // u0, sample1
        ull a11 = a01;                            // u1, sample1

        #pragma unroll
        for (int g = 0; g < 12; g++) {
            const ulonglong2 v0 = vp0[g];
            const ulonglong2 v1 = vp1[g];
            asm("fma.rn.f32x2 %0, %1, %2, %0;" : "+l"(a00) : "l"(v0.x), "l"(W0[2 * g]));
            asm("fma.rn.f32x2 %0, %1, %2, %0;" : "+l"(a01) : "l"(v0.x), "l"(W1[2 * g]));
            asm("fma.rn.f32x2 %0, %1, %2, %0;" : "+l"(a10) : "l"(v1.x), "l"(W0[2 * g]));
            asm("fma.rn.f32x2 %0, %1, %2, %0;" : "+l"(a11) : "l"(v1.x), "l"(W1[2 * g]));
            asm("fma.rn.f32x2 %0, %1, %2, %0;" : "+l"(a00) : "l"(v0.y), "l"(W0[2 * g + 1]));
            asm("fma.rn.f32x2 %0, %1, %2, %0;" : "+l"(a01) : "l"(v0.y), "l"(W1[2 * g + 1]));
            asm("fma.rn.f32x2 %0, %1, %2, %0;" : "+l"(a10) : "l"(v1.y), "l"(W0[2 * g + 1]));
            asm("fma.rn.f32x2 %0, %1, %2, %0;" : "+l"(a11) : "l"(v1.y), "l"(W1[2 * g + 1]));
        }

        // horizontal add each chain -> 4 partial scalars; publish
        float r00x, r00y, r01x, r01y, r10x, r10y, r11x, r11y;
        asm("mov.b64 {%0, %1}, %2;" : "=f"(r00x), "=f"(r00y) : "l"(a00));
        asm("mov.b64 {%0, %1}, %2;" : "=f"(r01x), "=f"(r01y) : "l"(a01));
        asm("mov.b64 {%0, %1}, %2;" : "=f"(r10x), "=f"(r10y) : "l"(a10));
        asm("mov.b64 {%0, %1}, %2;" : "=f"(r11x), "=f"(r11y) : "l"(a11));

        *reinterpret_cast<float2*>(&part[w][0][u0]) = make_float2(r00x + r00y, r01x + r01y);
        *reinterpret_cast<float2*>(&part[w][1][u0]) = make_float2(r10x + r10y, r11x + r11y);
        __syncthreads();

        // warp w finishes sample w: combine halves, tanh, publish h and x
        const float2 pa = *reinterpret_cast<const float2*>(&part[0][w][u0]);
        const float2 pb = *reinterpret_cast<const float2*>(&part[1][w][u0]);
        h0 = tanh_acc(pa.x + pb.x);
        h1 = tanh_acc(pa.y + pb.y);

        *reinterpret_cast<float2*>(&buf[nxt][w][u0]) = make_float2(h0, h1);
        buf[nxt][w][64 + l] = xn;
        __syncthreads();
    }

    // ---- output head: warp w reduces sample w ----
    float p = h0 * fc_w[u0] + h1 * fc_w[u1];
    #pragma unroll
    for (int o = 16; o; o >>= 1) p += __shfl_xor_sync(0xffffffffu, p, o);
    if (l == 0)
        out[n0 + w] = __fdividef(1.0f, 1.0f + __expf(-(p + fc_b[0])));
}

extern "C" void kernel_launch(void* const* d_in, const int* in_sizes, int n_in,
                              void* d_out, int out_size) {
    const float* x    = (const float*)d_in[0];
    const float* W_ih = (const float*)d_in[1];
    const float* W_hh = (const float*)d_in[2];
    const float* b_ih = (const float*)d_in[3];
    const float* b_hh = (const float*)d_in[4];
    const float* fc_w = (const float*)d_in[5];
    const float* fc_b = (const float*)d_in[6];
    float* out = (float*)d_out;

    rnn_ksplit_kernel<<<1024, 64>>>(x, W_ih, W_hh, b_ih, b_hh, fc_w, fc_b, out);
}